// round 4
// baseline (speedup 1.0000x reference)
#include <cuda_runtime.h>
#include <math.h>

#define BB 32
#define SS 4096
#define DD 1024
#define OO 1024
#define WIN 96                 // Gaussian window half-width: exp(-96^2/128)=5e-32, negligible
#define INV2SS (1.0f/128.0f)   // 1/(2*STDDEV^2), STDDEV=8
#define KS 16                  // K-splits for epilogue GEMM (2048/128)
#define KT 128                 // K per split
#define OT 64                  // output cols per block

// Scratch (no allocs allowed anywhere)
__device__ float g_score[BB * SS];        // 512 KB
__device__ float g_max[BB];
__device__ float g_sum[BB];
__device__ float g_weighted[BB * DD];     // 128 KB
__device__ float g_part[KS * BB * OO];    // 2 MB split-K partials

// ---------------------------------------------------------------------------
// Kernel 1: score[b,s] = dot(source[b,s,:], target[b,:])
// grid (S/64, B), 256 threads. 8 warps; each warp: 8 rows, 2 rows in flight
// (16 outstanding float4 loads) to overlap the shfl reduction with loads.
// ---------------------------------------------------------------------------
__global__ void __launch_bounds__(256) score_kernel(const float* __restrict__ src,
                                                    const float* __restrict__ tgt) {
    __shared__ float4 st[DD / 4];   // target row, 4 KB
    const int b = blockIdx.y;
    const int tid = threadIdx.x;

    st[tid] = reinterpret_cast<const float4*>(tgt + (size_t)b * DD)[tid];
    __syncthreads();

    const int warp = tid >> 5, lane = tid & 31;
    const int row0 = blockIdx.x * 64 + warp * 8;

    #pragma unroll
    for (int i = 0; i < 8; i += 2) {
        const float4* sa = reinterpret_cast<const float4*>(
            src + ((size_t)b * SS + row0 + i) * DD);
        const float4* sb = reinterpret_cast<const float4*>(
            src + ((size_t)b * SS + row0 + i + 1) * DD);
        float4 va[8], vb[8];
        #pragma unroll
        for (int k = 0; k < 8; k++) va[k] = __ldcs(sa + lane + 32 * k);
        #pragma unroll
        for (int k = 0; k < 8; k++) vb[k] = __ldcs(sb + lane + 32 * k);

        float4 a = make_float4(0.f, 0.f, 0.f, 0.f);
        float4 c = make_float4(0.f, 0.f, 0.f, 0.f);
        #pragma unroll
        for (int k = 0; k < 8; k++) {
            float4 t = st[lane + 32 * k];
            a.x += va[k].x * t.x; a.y += va[k].y * t.y;
            a.z += va[k].z * t.z; a.w += va[k].w * t.w;
            c.x += vb[k].x * t.x; c.y += vb[k].y * t.y;
            c.z += vb[k].z * t.z; c.w += vb[k].w * t.w;
        }
        float r0 = (a.x + a.y) + (a.z + a.w);
        float r1 = (c.x + c.y) + (c.z + c.w);
        #pragma unroll
        for (int off = 16; off; off >>= 1) {
            r0 += __shfl_xor_sync(0xffffffffu, r0, off);
            r1 += __shfl_xor_sync(0xffffffffu, r1, off);
        }
        if (lane == 0) {
            g_score[b * SS + row0 + i]     = r0;
            g_score[b * SS + row0 + i + 1] = r1;
        }
    }
}

// ---------------------------------------------------------------------------
// Kernel 2: per-batch softmax stats (max, sum of exp). grid B, 512 threads.
// ---------------------------------------------------------------------------
__global__ void __launch_bounds__(512) stats_kernel() {
    const int b = blockIdx.x, tid = threadIdx.x;
    const int warp = tid >> 5, lane = tid & 31;

    const float4* row4 = reinterpret_cast<const float4*>(g_score + b * SS);
    float4 v0 = row4[tid], v1 = row4[tid + 512];
    float m = fmaxf(fmaxf(fmaxf(v0.x, v0.y), fmaxf(v0.z, v0.w)),
                    fmaxf(fmaxf(v1.x, v1.y), fmaxf(v1.z, v1.w)));

    __shared__ float redm[16];
    __shared__ float reds[16];
    #pragma unroll
    for (int off = 16; off; off >>= 1)
        m = fmaxf(m, __shfl_xor_sync(0xffffffffu, m, off));
    if (lane == 0) redm[warp] = m;
    __syncthreads();
    if (tid < 32) {
        float mm = (tid < 16) ? redm[tid] : -1e30f;
        #pragma unroll
        for (int off = 8; off; off >>= 1)
            mm = fmaxf(mm, __shfl_xor_sync(0xffffffffu, mm, off));
        if (tid == 0) redm[0] = mm;
    }
    __syncthreads();
    m = redm[0];

    float s = expf(v0.x - m) + expf(v0.y - m) + expf(v0.z - m) + expf(v0.w - m)
            + expf(v1.x - m) + expf(v1.y - m) + expf(v1.z - m) + expf(v1.w - m);
    #pragma unroll
    for (int off = 16; off; off >>= 1)
        s += __shfl_xor_sync(0xffffffffu, s, off);
    if (lane == 0) reds[warp] = s;
    __syncthreads();
    if (tid < 32) {
        float ss2 = (tid < 16) ? reds[tid] : 0.f;
        #pragma unroll
        for (int off = 8; off; off >>= 1)
            ss2 += __shfl_xor_sync(0xffffffffu, ss2, off);
        if (tid == 0) { g_max[b] = m; g_sum[b] = ss2; }
    }
}

// ---------------------------------------------------------------------------
// Kernel 3: weighted[b,d] = sum over the +-WIN window of w[b,s]*source[b,s,d]
// grid (D/256, B), 256 threads, thread-per-d, manual unroll-by-4 for MLP.
// ---------------------------------------------------------------------------
__global__ void __launch_bounds__(256) weighted_kernel(const float* __restrict__ src,
                                                       const int* __restrict__ pos) {
    __shared__ float wc[2 * WIN + 1];   // 193 coefficients
    const int b = blockIdx.y;
    const int tid = threadIdx.x;
    const int p = pos[b];
    const int s0 = max(0, p - WIN);
    const int s1 = min(SS - 1, p + WIN);
    const int n = s1 - s0 + 1;

    if (tid < n) {
        const int s = s0 + tid;
        const float rel = (float)(s - p);
        wc[tid] = expf(g_score[b * SS + s] - g_max[b]) * (1.0f / g_sum[b])
                * expf(-rel * rel * INV2SS);
    }
    __syncthreads();

    const int d = blockIdx.x * 256 + tid;
    const float* sp = src + ((size_t)b * SS + s0) * DD + d;
    float acc = 0.f;
    int i = 0;
    for (; i + 4 <= n; i += 4) {        // 4 independent loads in flight
        float x0 = sp[(size_t)(i + 0) * DD];
        float x1 = sp[(size_t)(i + 1) * DD];
        float x2 = sp[(size_t)(i + 2) * DD];
        float x3 = sp[(size_t)(i + 3) * DD];
        acc += wc[i] * x0 + wc[i + 1] * x1 + wc[i + 2] * x2 + wc[i + 3] * x3;
    }
    for (; i < n; i++)
        acc += wc[i] * sp[(size_t)i * DD];
    g_weighted[b * DD + d] = acc;
}

// ---------------------------------------------------------------------------
// Kernel 4a: split-K partial GEMM, no W staging. C=[32,2048], W=[2048,1024].
// grid (16 otiles, 16 ks) = 256 blocks, 256 threads.
// Thread (oc=tid&63, bq=tid>>6): 8 batches x 1 col; W read directly from
// global, coalesced, unrolled x8 -> 8 loads feeding 64 FMAs per chunk.
// K slices of 128 align with the concat boundary at 1024.
// ---------------------------------------------------------------------------
__global__ void __launch_bounds__(256) out_partial(const float* __restrict__ tgt,
                                                   const float* __restrict__ Wm) {
    __shared__ float sC[BB][KT];       // 16 KB
    const int tid = threadIdx.x;
    const int obase = blockIdx.x * OT;
    const int ks = blockIdx.y;
    const int kg0 = ks * KT;
    const float* cbase = (kg0 < DD) ? tgt : g_weighted;
    const int koff = kg0 & (DD - 1);

    // stage C slice [32][128] via float4: 1024 float4, 4 per thread
    float4* sC4 = reinterpret_cast<float4*>(&sC[0][0]);
    #pragma unroll
    for (int j = 0; j < 4; j++) {
        const int e = tid + 256 * j;           // e = row*32 + c4
        sC4[e] = reinterpret_cast<const float4*>(
            cbase + (e >> 5) * DD + koff)[e & 31];
    }
    __syncthreads();

    const int oc = tid & 63;       // consecutive within warp -> coalesced W
    const int bq = tid >> 6;       // 0..3, each owns 8 batches
    const float* wp = Wm + (size_t)kg0 * OO + obase + oc;

    float acc[8];
    #pragma unroll
    for (int i = 0; i < 8; i++) acc[i] = 0.f;

    for (int kk = 0; kk < KT; kk += 8) {
        float w[8];
        #pragma unroll
        for (int u = 0; u < 8; u++)
            w[u] = __ldg(wp + (size_t)(kk + u) * OO);   // 8 loads in flight
        #pragma unroll
        for (int u = 0; u < 8; u++) {
            #pragma unroll
            for (int i = 0; i < 8; i++)
                acc[i] += sC[bq * 8 + i][kk + u] * w[u];  // smem broadcast
        }
    }

    #pragma unroll
    for (int i = 0; i < 8; i++)
        g_part[((size_t)ks * BB + bq * 8 + i) * OO + obase + oc] = acc[i];
}

// ---------------------------------------------------------------------------
// Kernel 4b: out[b,o] = tanh(sum_ks part[ks,b,o]). float4, 8192 lanes.
// ---------------------------------------------------------------------------
__global__ void __launch_bounds__(256) out_reduce(float* __restrict__ out) {
    const int i4 = blockIdx.x * 256 + threadIdx.x;   // float4 index into [B*O]
    const float4* p4 = reinterpret_cast<const float4*>(g_part);
    float4 s = make_float4(0.f, 0.f, 0.f, 0.f);
    #pragma unroll
    for (int ks = 0; ks < KS; ks++) {
        float4 v = p4[(size_t)ks * (BB * OO / 4) + i4];
        s.x += v.x; s.y += v.y; s.z += v.z; s.w += v.w;
    }
    float4 r = make_float4(tanhf(s.x), tanhf(s.y), tanhf(s.z), tanhf(s.w));
    reinterpret_cast<float4*>(out)[i4] = r;
}

// ---------------------------------------------------------------------------
extern "C" void kernel_launch(void* const* d_in, const int* in_sizes, int n_in,
                              void* d_out, int out_size) {
    const float* src = (const float*)d_in[0];   // [B,S,D]
    const float* tgt = (const float*)d_in[1];   // [B,D]
    const int*   pos = (const int*)d_in[2];     // [B]
    const float* Wm  = (const float*)d_in[3];   // [2D,O]
    float* out = (float*)d_out;                 // [B,O]

    score_kernel<<<dim3(SS / 64, BB), 256>>>(src, tgt);
    stats_kernel<<<BB, 512>>>();
    weighted_kernel<<<dim3(DD / 256, BB), 256>>>(src, pos);
    out_partial<<<dim3(OO / OT, KS), 256>>>(tgt, Wm);
    out_reduce<<<BB * OO / 4 / 256, 256>>>(out);
}

// round 5
// speedup vs baseline: 1.1838x; 1.1838x over previous
#include <cuda_runtime.h>
#include <math.h>

#define BB 32
#define SS 4096
#define DD 1024
#define OO 1024
#define NBLK 64                // score blocks per batch (SS/64)
#define WIN 96                 // Gaussian window half-width: exp(-96^2/128)=5e-32, negligible
#define INV2SS (1.0f/128.0f)   // 1/(2*STDDEV^2), STDDEV=8
#define KS 16                  // K-splits for epilogue GEMM (2048/128)
#define KT 128                 // K per split
#define OT 64                  // output cols per block

// Scratch (no allocs allowed anywhere)
__device__ float g_score[BB * SS];        // 512 KB
__device__ float g_bmax[BB * NBLK];       // per-score-block max
__device__ float g_bsum[BB * NBLK];       // per-score-block sum of exp(.-bmax)
__device__ float g_max[BB];
__device__ float g_sum[BB];
__device__ float g_weighted[BB * DD];     // 128 KB
__device__ float g_part[KS * BB * OO];    // 2 MB split-K partials

// ---------------------------------------------------------------------------
// Kernel 1: score[b,s] = dot(source[b,s,:], target[b,:]) + in-block softmax
// partials. grid (S/64, B), 256 threads. 8 warps; each warp: 8 rows, 2 rows
// in flight (16 outstanding float4 loads). Owns the 512 MB traffic floor.
// ---------------------------------------------------------------------------
__global__ void __launch_bounds__(256) score_kernel(const float* __restrict__ src,
                                                    const float* __restrict__ tgt) {
    __shared__ float4 st[DD / 4];   // target row, 4 KB
    __shared__ float sc[64];        // block's 64 scores for stats reduction
    const int b = blockIdx.y;
    const int tid = threadIdx.x;

    st[tid] = reinterpret_cast<const float4*>(tgt + (size_t)b * DD)[tid];
    __syncthreads();

    const int warp = tid >> 5, lane = tid & 31;
    const int row0 = blockIdx.x * 64 + warp * 8;

    #pragma unroll
    for (int i = 0; i < 8; i += 2) {
        const float4* sa = reinterpret_cast<const float4*>(
            src + ((size_t)b * SS + row0 + i) * DD);
        const float4* sb = reinterpret_cast<const float4*>(
            src + ((size_t)b * SS + row0 + i + 1) * DD);
        float4 va[8], vb[8];
        #pragma unroll
        for (int k = 0; k < 8; k++) va[k] = __ldcs(sa + lane + 32 * k);
        #pragma unroll
        for (int k = 0; k < 8; k++) vb[k] = __ldcs(sb + lane + 32 * k);

        float4 a = make_float4(0.f, 0.f, 0.f, 0.f);
        float4 c = make_float4(0.f, 0.f, 0.f, 0.f);
        #pragma unroll
        for (int k = 0; k < 8; k++) {
            float4 t = st[lane + 32 * k];
            a.x += va[k].x * t.x; a.y += va[k].y * t.y;
            a.z += va[k].z * t.z; a.w += va[k].w * t.w;
            c.x += vb[k].x * t.x; c.y += vb[k].y * t.y;
            c.z += vb[k].z * t.z; c.w += vb[k].w * t.w;
        }
        float r0 = (a.x + a.y) + (a.z + a.w);
        float r1 = (c.x + c.y) + (c.z + c.w);
        #pragma unroll
        for (int off = 16; off; off >>= 1) {
            r0 += __shfl_xor_sync(0xffffffffu, r0, off);
            r1 += __shfl_xor_sync(0xffffffffu, r1, off);
        }
        if (lane == 0) {
            g_score[b * SS + row0 + i]     = r0;
            g_score[b * SS + row0 + i + 1] = r1;
            sc[warp * 8 + i]     = r0;
            sc[warp * 8 + i + 1] = r1;
        }
    }

    // block-level softmax partials over the 64 scores (one warp)
    __syncthreads();
    if (tid < 32) {
        const float x0 = sc[tid], x1 = sc[tid + 32];
        float m = fmaxf(x0, x1);
        #pragma unroll
        for (int off = 16; off; off >>= 1)
            m = fmaxf(m, __shfl_xor_sync(0xffffffffu, m, off));
        float s = expf(x0 - m) + expf(x1 - m);
        #pragma unroll
        for (int off = 16; off; off >>= 1)
            s += __shfl_xor_sync(0xffffffffu, s, off);
        if (tid == 0) {
            g_bmax[b * NBLK + blockIdx.x] = m;
            g_bsum[b * NBLK + blockIdx.x] = s;
        }
    }
}

// ---------------------------------------------------------------------------
// Kernel 2: merge per-block softmax partials (log-sum-exp). grid B, 32 thr.
// ---------------------------------------------------------------------------
__global__ void __launch_bounds__(32) stats_merge() {
    const int b = blockIdx.x, tid = threadIdx.x;
    const float m0 = g_bmax[b * NBLK + tid];
    const float m1 = g_bmax[b * NBLK + tid + 32];
    const float s0 = g_bsum[b * NBLK + tid];
    const float s1 = g_bsum[b * NBLK + tid + 32];

    float m = fmaxf(m0, m1);
    #pragma unroll
    for (int off = 16; off; off >>= 1)
        m = fmaxf(m, __shfl_xor_sync(0xffffffffu, m, off));
    float s = s0 * expf(m0 - m) + s1 * expf(m1 - m);
    #pragma unroll
    for (int off = 16; off; off >>= 1)
        s += __shfl_xor_sync(0xffffffffu, s, off);
    if (tid == 0) { g_max[b] = m; g_sum[b] = s; }
}

// ---------------------------------------------------------------------------
// Kernel 3: weighted[b,d] = sum over the +-WIN window of w[b,s]*source[b,s,d]
// grid (D/256, B), 256 threads, thread-per-d. Only ~25 MB of source touched.
// ---------------------------------------------------------------------------
__global__ void __launch_bounds__(256) weighted_kernel(const float* __restrict__ src,
                                                       const int* __restrict__ pos) {
    __shared__ float wc[2 * WIN + 1];   // 193 coefficients
    const int b = blockIdx.y;
    const int tid = threadIdx.x;
    const int p = pos[b];
    const int s0 = max(0, p - WIN);
    const int s1 = min(SS - 1, p + WIN);
    const int n = s1 - s0 + 1;

    if (tid < n) {
        const int s = s0 + tid;
        const float rel = (float)(s - p);
        wc[tid] = expf(g_score[b * SS + s] - g_max[b]) * (1.0f / g_sum[b])
                * expf(-rel * rel * INV2SS);
    }
    __syncthreads();

    const int d = blockIdx.x * 256 + tid;
    const float* sp = src + ((size_t)b * SS + s0) * DD + d;
    float acc = 0.f;
    for (int i = 0; i < n; i++)
        acc += wc[i] * sp[(size_t)i * DD];   // coalesced 1KB rows
    g_weighted[b * DD + d] = acc;
}

// ---------------------------------------------------------------------------
// Kernel 4a: split-K partial GEMM (R2 known-good: 12.0us). C=[32,2048],
// W=[2048,1024]. grid (16 otiles, 16 ks) = 256 blocks, 256 threads.
// Both tiles staged via float4 (staging loop provides the MLP).
// K slices of 128 align with the concat boundary at 1024.
// ---------------------------------------------------------------------------
__global__ void __launch_bounds__(256) out_partial(const float* __restrict__ tgt,
                                                   const float* __restrict__ Wm) {
    __shared__ float sC[BB][KT];       // 16 KB
    __shared__ float sW[KT][OT];       // 32 KB
    const int tid = threadIdx.x;
    const int obase = blockIdx.x * OT;
    const int ks = blockIdx.y;
    const int kg0 = ks * KT;
    const float* cbase = (kg0 < DD) ? tgt : g_weighted;
    const int koff = kg0 & (DD - 1);

    // stage C slice [32][128] via float4: 1024 float4, 4 per thread
    float4* sC4 = reinterpret_cast<float4*>(&sC[0][0]);
    #pragma unroll
    for (int j = 0; j < 4; j++) {
        const int e = tid + 256 * j;           // e = row*32 + c4
        sC4[e] = reinterpret_cast<const float4*>(
            cbase + (e >> 5) * DD + koff)[e & 31];
    }
    // stage W slice [128][64] via float4: 2048 float4, 8 per thread
    float4* sW4 = reinterpret_cast<float4*>(&sW[0][0]);
    #pragma unroll
    for (int j = 0; j < 8; j++) {
        const int e = tid + 256 * j;           // e = k*16 + c4
        sW4[e] = reinterpret_cast<const float4*>(
            Wm + (size_t)(kg0 + (e >> 4)) * OO + obase)[e & 15];
    }
    __syncthreads();

    const int oc = tid & 63;       // consecutive within warp -> conflict-free sW
    const int bq = tid >> 6;       // 0..3, each owns 8 batches
    float acc[8];
    #pragma unroll
    for (int i = 0; i < 8; i++) acc[i] = 0.f;

    #pragma unroll 4
    for (int k = 0; k < KT; k++) {
        const float w = sW[k][oc];
        #pragma unroll
        for (int i = 0; i < 8; i++)
            acc[i] += sC[bq * 8 + i][k] * w;   // broadcast reads
    }

    #pragma unroll
    for (int i = 0; i < 8; i++)
        g_part[((size_t)ks * BB + bq * 8 + i) * OO + obase + oc] = acc[i];
}

// ---------------------------------------------------------------------------
// Kernel 4b: out[b,o] = tanh(sum_ks part[ks,b,o]). float4, 8192 lanes.
// ---------------------------------------------------------------------------
__global__ void __launch_bounds__(256) out_reduce(float* __restrict__ out) {
    const int i4 = blockIdx.x * 256 + threadIdx.x;   // float4 index into [B*O]
    const float4* p4 = reinterpret_cast<const float4*>(g_part);
    float4 s = make_float4(0.f, 0.f, 0.f, 0.f);
    #pragma unroll
    for (int ks = 0; ks < KS; ks++) {
        float4 v = p4[(size_t)ks * (BB * OO / 4) + i4];
        s.x += v.x; s.y += v.y; s.z += v.z; s.w += v.w;
    }
    float4 r = make_float4(tanhf(s.x), tanhf(s.y), tanhf(s.z), tanhf(s.w));
    reinterpret_cast<float4*>(out)[i4] = r;
}

// ---------------------------------------------------------------------------
extern "C" void kernel_launch(void* const* d_in, const int* in_sizes, int n_in,
                              void* d_out, int out_size) {
    const float* src = (const float*)d_in[0];   // [B,S,D]
    const float* tgt = (const float*)d_in[1];   // [B,D]
    const int*   pos = (const int*)d_in[2];     // [B]
    const float* Wm  = (const float*)d_in[3];   // [2D,O]
    float* out = (float*)d_out;                 // [B,O]

    score_kernel<<<dim3(SS / 64, BB), 256>>>(src, tgt);
    stats_merge<<<BB, 32>>>();
    weighted_kernel<<<dim3(DD / 256, BB), 256>>>(src, pos);
    out_partial<<<dim3(OO / OT, KS), 256>>>(tgt, Wm);
    out_reduce<<<BB * OO / 4 / 256, 256>>>(out);
}

// round 7
// speedup vs baseline: 1.2763x; 1.0781x over previous
#include <cuda_runtime.h>
#include <math.h>

#define BB 32
#define SS 4096
#define DD 1024
#define OO 1024
#define NBLK 64                // score blocks per batch (SS/64)
#define WIN 96                 // Gaussian window half-width: exp(-96^2/128)=5e-32, negligible
#define INV2SS (1.0f/128.0f)   // 1/(2*STDDEV^2), STDDEV=8
#define KS 16                  // K-splits for epilogue GEMM (2048/128)
#define KT 128                 // K per split
#define OT 64                  // output cols per block
#define WSPLIT 4               // window splits for weighted kernel

// Scratch (no allocs allowed anywhere)
__device__ float g_score[BB * SS];        // 512 KB
__device__ float g_bmax[BB * NBLK];       // per-score-block max
__device__ float g_bsum[BB * NBLK];       // per-score-block sum of exp(.-bmax)
__device__ float g_max[BB];
__device__ float g_sum[BB];
__device__ float g_wpart[WSPLIT * BB * DD];  // 512 KB weighted partials
__device__ float g_weighted[BB * DD];     // 128 KB
__device__ float g_part[KS * BB * OO];    // 2 MB split-K partials

// ---------------------------------------------------------------------------
// Kernel 1: score[b,s] = dot(source[b,s,:], target[b,:]) + block softmax
// partials. grid (S/64, B), 256 threads, 8 warps x 8 rows.
// Key change vs R5: NO shfl reduction inside the load loop — each lane STSes
// its per-row partial; a single block-wide pass reduces all 64 rows at the
// end. The 8-row loop is a pure load+FMA stream ptxas can pipeline.
// ---------------------------------------------------------------------------
__global__ void __launch_bounds__(256) score_kernel(const float* __restrict__ src,
                                                    const float* __restrict__ tgt) {
    __shared__ float4 st[DD / 4];     // target row, 4 KB
    __shared__ float sc2[64 * 33];    // per-(row,lane) partials, padded, 8.25 KB
    __shared__ float scs[64];         // final 64 row scores
    const int b = blockIdx.y;
    const int tid = threadIdx.x;

    st[tid] = reinterpret_cast<const float4*>(tgt + (size_t)b * DD)[tid];
    __syncthreads();

    const int warp = tid >> 5, lane = tid & 31;
    const int row0 = blockIdx.x * 64 + warp * 8;

    #pragma unroll
    for (int i = 0; i < 8; i++) {
        const float4* s4 = reinterpret_cast<const float4*>(
            src + ((size_t)b * SS + row0 + i) * DD);
        float4 a = make_float4(0.f, 0.f, 0.f, 0.f);
        #pragma unroll
        for (int k = 0; k < 8; k++) {
            float4 v = __ldcs(s4 + lane + 32 * k);
            float4 t = st[lane + 32 * k];
            a.x += v.x * t.x; a.y += v.y * t.y;
            a.z += v.z * t.z; a.w += v.w * t.w;
        }
        sc2[(warp * 8 + i) * 33 + lane] = (a.x + a.y) + (a.z + a.w);
    }
    __syncthreads();

    // reduce 64 rows: 4 threads/row, each sums 8 lanes, then 2 shfl steps.
    // bank = (row + q*8 + j) & 31 -> conflict-free thanks to the *33 pad.
    {
        const int row = tid >> 2, q = tid & 3;
        float s = 0.f;
        #pragma unroll
        for (int j = 0; j < 8; j++) s += sc2[row * 33 + q * 8 + j];
        s += __shfl_xor_sync(0xffffffffu, s, 1);
        s += __shfl_xor_sync(0xffffffffu, s, 2);
        if (q == 0) {
            g_score[b * SS + blockIdx.x * 64 + row] = s;
            scs[row] = s;
        }
    }
    __syncthreads();

    // block-level softmax partials over the 64 scores (one warp)
    if (tid < 32) {
        const float x0 = scs[tid], x1 = scs[tid + 32];
        float m = fmaxf(x0, x1);
        #pragma unroll
        for (int off = 16; off; off >>= 1)
            m = fmaxf(m, __shfl_xor_sync(0xffffffffu, m, off));
        float s = expf(x0 - m) + expf(x1 - m);
        #pragma unroll
        for (int off = 16; off; off >>= 1)
            s += __shfl_xor_sync(0xffffffffu, s, off);
        if (tid == 0) {
            g_bmax[b * NBLK + blockIdx.x] = m;
            g_bsum[b * NBLK + blockIdx.x] = s;
        }
    }
}

// ---------------------------------------------------------------------------
// Kernel 2: merge per-block softmax partials (log-sum-exp). grid B, 32 thr.
// ---------------------------------------------------------------------------
__global__ void __launch_bounds__(32) stats_merge() {
    const int b = blockIdx.x, tid = threadIdx.x;
    const float m0 = g_bmax[b * NBLK + tid];
    const float m1 = g_bmax[b * NBLK + tid + 32];
    const float s0 = g_bsum[b * NBLK + tid];
    const float s1 = g_bsum[b * NBLK + tid + 32];

    float m = fmaxf(m0, m1);
    #pragma unroll
    for (int off = 16; off; off >>= 1)
        m = fmaxf(m, __shfl_xor_sync(0xffffffffu, m, off));
    float s = s0 * expf(m0 - m) + s1 * expf(m1 - m);
    #pragma unroll
    for (int off = 16; off; off >>= 1)
        s += __shfl_xor_sync(0xffffffffu, s, off);
    if (tid == 0) { g_max[b] = m; g_sum[b] = s; }
}

// ---------------------------------------------------------------------------
// Kernel 3: weighted partials, window split 4 ways.
// grid (D/256, B, WSPLIT), 256 threads; each z handles ~n/4 window rows.
// 512 blocks total -> enough concurrency to hide DRAM latency on 25 MB.
// ---------------------------------------------------------------------------
__global__ void __launch_bounds__(256) weighted_kernel(const float* __restrict__ src,
                                                       const int* __restrict__ pos) {
    __shared__ float wc[64];          // this split's coefficients (<=49)
    const int b = blockIdx.y;
    const int z = blockIdx.z;
    const int tid = threadIdx.x;
    const int p = pos[b];
    const int s0 = max(0, p - WIN);
    const int s1 = min(SS - 1, p + WIN);
    const int n = s1 - s0 + 1;
    const int cl = (n + WSPLIT - 1) / WSPLIT;      // chunk length
    const int c0 = z * cl;                          // chunk start (rel)
    const int cn = min(cl, n - c0);                 // chunk rows (may be <=0)

    if (tid < cl && tid < cn) {
        const int s = s0 + c0 + tid;
        const float rel = (float)(s - p);
        wc[tid] = expf(g_score[b * SS + s] - g_max[b]) * (1.0f / g_sum[b])
                * expf(-rel * rel * INV2SS);
    }
    __syncthreads();

    const int d = blockIdx.x * 256 + tid;
    const float* sp = src + ((size_t)b * SS + s0 + c0) * DD + d;
    float acc = 0.f;
    for (int i = 0; i < cn; i++)
        acc += wc[i] * sp[(size_t)i * DD];   // coalesced 1KB rows
    g_wpart[((size_t)z * BB + b) * DD + d] = acc;
}

// ---------------------------------------------------------------------------
// Kernel 3b: g_weighted = sum of the 4 window partials. float4, 8192 lanes.
// ---------------------------------------------------------------------------
__global__ void __launch_bounds__(256) wmerge() {
    const int i4 = blockIdx.x * 256 + threadIdx.x;   // float4 index into [B*D]
    const float4* p4 = reinterpret_cast<const float4*>(g_wpart);
    float4 s = make_float4(0.f, 0.f, 0.f, 0.f);
    #pragma unroll
    for (int z = 0; z < WSPLIT; z++) {
        float4 v = p4[(size_t)z * (BB * DD / 4) + i4];
        s.x += v.x; s.y += v.y; s.z += v.z; s.w += v.w;
    }
    reinterpret_cast<float4*>(g_weighted)[i4] = s;
}

// ---------------------------------------------------------------------------
// Kernel 4a: split-K partial GEMM (R2/R5 known-good: ~11us). C=[32,2048],
// W=[2048,1024]. grid (16 otiles, 16 ks) = 256 blocks, 256 threads.
// Both tiles staged via float4 (staging loop provides the MLP).
// ---------------------------------------------------------------------------
__global__ void __launch_bounds__(256) out_partial(const float* __restrict__ tgt,
                                                   const float* __restrict__ Wm) {
    __shared__ float sC[BB][KT];       // 16 KB
    __shared__ float sW[KT][OT];       // 32 KB
    const int tid = threadIdx.x;
    const int obase = blockIdx.x * OT;
    const int ks = blockIdx.y;
    const int kg0 = ks * KT;
    const float* cbase = (kg0 < DD) ? tgt : g_weighted;
    const int koff = kg0 & (DD - 1);

    float4* sC4 = reinterpret_cast<float4*>(&sC[0][0]);
    #pragma unroll
    for (int j = 0; j < 4; j++) {
        const int e = tid + 256 * j;           // e = row*32 + c4
        sC4[e] = reinterpret_cast<const float4*>(
            cbase + (e >> 5) * DD + koff)[e & 31];
    }
    float4* sW4 = reinterpret_cast<float4*>(&sW[0][0]);
    #pragma unroll
    for (int j = 0; j < 8; j++) {
        const int e = tid + 256 * j;           // e = k*16 + c4
        sW4[e] = reinterpret_cast<const float4*>(
            Wm + (size_t)(kg0 + (e >> 4)) * OO + obase)[e & 15];
    }
    __syncthreads();

    const int oc = tid & 63;
    const int bq = tid >> 6;
    float acc[8];
    #pragma unroll
    for (int i = 0; i < 8; i++) acc[i] = 0.f;

    #pragma unroll 4
    for (int k = 0; k < KT; k++) {
        const float w = sW[k][oc];
        #pragma unroll
        for (int i = 0; i < 8; i++)
            acc[i] += sC[bq * 8 + i][k] * w;   // broadcast reads
    }

    #pragma unroll
    for (int i = 0; i < 8; i++)
        g_part[((size_t)ks * BB + bq * 8 + i) * OO + obase + oc] = acc[i];
}

// ---------------------------------------------------------------------------
// Kernel 4b: out[b,o] = tanh(sum_ks part[ks,b,o]). float4, 8192 lanes.
// ---------------------------------------------------------------------------
__global__ void __launch_bounds__(256) out_reduce(float* __restrict__ out) {
    const int i4 = blockIdx.x * 256 + threadIdx.x;
    const float4* p4 = reinterpret_cast<const float4*>(g_part);
    float4 s = make_float4(0.f, 0.f, 0.f, 0.f);
    #pragma unroll
    for (int ks = 0; ks < KS; ks++) {
        float4 v = p4[(size_t)ks * (BB * OO / 4) + i4];
        s.x += v.x; s.y += v.y; s.z += v.z; s.w += v.w;
    }
    float4 r = make_float4(tanhf(s.x), tanhf(s.y), tanhf(s.z), tanhf(s.w));
    reinterpret_cast<float4*>(out)[i4] = r;
}

// ---------------------------------------------------------------------------
extern "C" void kernel_launch(void* const* d_in, const int* in_sizes, int n_in,
                              void* d_out, int out_size) {
    const float* src = (const float*)d_in[0];   // [B,S,D]
    const float* tgt = (const float*)d_in[1];   // [B,D]
    const int*   pos = (const int*)d_in[2];     // [B]
    const float* Wm  = (const float*)d_in[3];   // [2D,O]
    float* out = (float*)d_out;                 // [B,O]

    score_kernel<<<dim3(SS / 64, BB), 256>>>(src, tgt);
    stats_merge<<<BB, 32>>>();
    weighted_kernel<<<dim3(DD / 256, BB, WSPLIT), 256>>>(src, pos);
    wmerge<<<BB * DD / 4 / 256, 256>>>();
    out_partial<<<dim3(OO / OT, KS), 256>>>(tgt, Wm);
    out_reduce<<<BB * OO / 4 / 256, 256>>>(out);
}

// round 8
// speedup vs baseline: 1.3245x; 1.0378x over previous
#include <cuda_runtime.h>
#include <math.h>

#define BB 32
#define SS 4096
#define DD 1024
#define OO 1024
#define NBLK 64                // score blocks per batch (SS/64)
#define WIN 96                 // Gaussian window half-width: exp(-96^2/128)=5e-32, negligible
#define INV2SS (1.0f/128.0f)   // 1/(2*STDDEV^2), STDDEV=8
#define KS 16                  // K-splits for epilogue GEMM (2048/128)
#define KT 128                 // K per split
#define OT 64                  // output cols per block
#define WSPLIT 4               // window splits for weighted kernel

// Scratch (no allocs allowed anywhere)
__device__ float g_score[BB * SS];        // 512 KB
__device__ float g_bmax[BB * NBLK];       // per-score-block max
__device__ float g_bsum[BB * NBLK];       // per-score-block sum of exp(.-bmax)
__device__ float g_wpart[WSPLIT * BB * DD];  // 512 KB weighted partials
__device__ float g_part[KS * BB * OO];    // 2 MB split-K partials

// ---------------------------------------------------------------------------
// Kernel 1: score[b,s] = dot(source[b,s,:], target[b,:]) + block softmax
// partials. grid (S/64, B), 256 threads, 8 warps x 8 rows.
// No shfl reduction inside the load loop — each lane STSes its per-row
// partial; a single block-wide pass reduces all 64 rows at the end.
// ---------------------------------------------------------------------------
__global__ void __launch_bounds__(256) score_kernel(const float* __restrict__ src,
                                                    const float* __restrict__ tgt) {
    __shared__ float4 st[DD / 4];     // target row, 4 KB
    __shared__ float sc2[64 * 33];    // per-(row,lane) partials, padded, 8.25 KB
    __shared__ float scs[64];         // final 64 row scores
    const int b = blockIdx.y;
    const int tid = threadIdx.x;

    st[tid] = reinterpret_cast<const float4*>(tgt + (size_t)b * DD)[tid];
    __syncthreads();

    const int warp = tid >> 5, lane = tid & 31;
    const int row0 = blockIdx.x * 64 + warp * 8;

    #pragma unroll
    for (int i = 0; i < 8; i++) {
        const float4* s4 = reinterpret_cast<const float4*>(
            src + ((size_t)b * SS + row0 + i) * DD);
        float4 a = make_float4(0.f, 0.f, 0.f, 0.f);
        #pragma unroll
        for (int k = 0; k < 8; k++) {
            float4 v = __ldcs(s4 + lane + 32 * k);
            float4 t = st[lane + 32 * k];
            a.x += v.x * t.x; a.y += v.y * t.y;
            a.z += v.z * t.z; a.w += v.w * t.w;
        }
        sc2[(warp * 8 + i) * 33 + lane] = (a.x + a.y) + (a.z + a.w);
    }
    __syncthreads();

    // reduce 64 rows: 4 threads/row, each sums 8 lanes, then 2 shfl steps.
    {
        const int row = tid >> 2, q = tid & 3;
        float s = 0.f;
        #pragma unroll
        for (int j = 0; j < 8; j++) s += sc2[row * 33 + q * 8 + j];
        s += __shfl_xor_sync(0xffffffffu, s, 1);
        s += __shfl_xor_sync(0xffffffffu, s, 2);
        if (q == 0) {
            g_score[b * SS + blockIdx.x * 64 + row] = s;
            scs[row] = s;
        }
    }
    __syncthreads();

    // block-level softmax partials over the 64 scores (one warp)
    if (tid < 32) {
        const float x0 = scs[tid], x1 = scs[tid + 32];
        float m = fmaxf(x0, x1);
        #pragma unroll
        for (int off = 16; off; off >>= 1)
            m = fmaxf(m, __shfl_xor_sync(0xffffffffu, m, off));
        float s = expf(x0 - m) + expf(x1 - m);
        #pragma unroll
        for (int off = 16; off; off >>= 1)
            s += __shfl_xor_sync(0xffffffffu, s, off);
        if (tid == 0) {
            g_bmax[b * NBLK + blockIdx.x] = m;
            g_bsum[b * NBLK + blockIdx.x] = s;
        }
    }
}

// ---------------------------------------------------------------------------
// Kernel 2: weighted partials, window split 4 ways, with INLINE softmax
// stats merge (each block recomputes the 64-entry LSE merge — one warp,
// off the critical path, removes the stats_merge launch).
// grid (D/256, B, WSPLIT), 256 threads.
// ---------------------------------------------------------------------------
__global__ void __launch_bounds__(256) weighted_kernel(const float* __restrict__ src,
                                                       const int* __restrict__ pos) {
    __shared__ float wc[64];          // this split's coefficients (<=49)
    __shared__ float s_m, s_s;
    const int b = blockIdx.y;
    const int z = blockIdx.z;
    const int tid = threadIdx.x;

    // inline stats merge over the 64 score blocks of this batch
    if (tid < 32) {
        const float m0 = g_bmax[b * NBLK + tid];
        const float m1 = g_bmax[b * NBLK + tid + 32];
        const float s0 = g_bsum[b * NBLK + tid];
        const float s1 = g_bsum[b * NBLK + tid + 32];
        float m = fmaxf(m0, m1);
        #pragma unroll
        for (int off = 16; off; off >>= 1)
            m = fmaxf(m, __shfl_xor_sync(0xffffffffu, m, off));
        float s = s0 * expf(m0 - m) + s1 * expf(m1 - m);
        #pragma unroll
        for (int off = 16; off; off >>= 1)
            s += __shfl_xor_sync(0xffffffffu, s, off);
        if (tid == 0) { s_m = m; s_s = s; }
    }
    __syncthreads();

    const int p = pos[b];
    const int s0w = max(0, p - WIN);
    const int s1w = min(SS - 1, p + WIN);
    const int n = s1w - s0w + 1;
    const int cl = (n + WSPLIT - 1) / WSPLIT;      // chunk length
    const int c0 = z * cl;                          // chunk start (rel)
    const int cn = min(cl, n - c0);                 // chunk rows (may be <=0)

    if (tid < cl && tid < cn) {
        const int s = s0w + c0 + tid;
        const float rel = (float)(s - p);
        wc[tid] = expf(g_score[b * SS + s] - s_m) * (1.0f / s_s)
                * expf(-rel * rel * INV2SS);
    }
    __syncthreads();

    const int d = blockIdx.x * 256 + tid;
    const float* sp = src + ((size_t)b * SS + s0w + c0) * DD + d;
    float acc = 0.f;
    for (int i = 0; i < cn; i++)
        acc += wc[i] * sp[(size_t)i * DD];   // coalesced 1KB rows
    g_wpart[((size_t)z * BB + b) * DD + d] = acc;
}

// ---------------------------------------------------------------------------
// Kernel 3: split-K partial GEMM. C=[32,2048] (concat of target and
// sum-of-wpart), W=[2048,1024]. grid (16 otiles, 16 ks) = 256 blocks.
// For the weighted half, the C staging loop sums the 4 window partials
// inline (removes the wmerge launch; extra loads = extra staging MLP).
// ---------------------------------------------------------------------------
__global__ void __launch_bounds__(256) out_partial(const float* __restrict__ tgt,
                                                   const float* __restrict__ Wm) {
    __shared__ float sC[BB][KT];       // 16 KB
    __shared__ float sW[KT][OT];       // 32 KB
    const int tid = threadIdx.x;
    const int obase = blockIdx.x * OT;
    const int ks = blockIdx.y;
    const int kg0 = ks * KT;
    const int koff = kg0 & (DD - 1);

    float4* sC4 = reinterpret_cast<float4*>(&sC[0][0]);
    if (kg0 < DD) {
        // target half: 1024 float4, 4 per thread
        #pragma unroll
        for (int j = 0; j < 4; j++) {
            const int e = tid + 256 * j;           // e = row*32 + c4
            sC4[e] = reinterpret_cast<const float4*>(
                tgt + (e >> 5) * DD + koff)[e & 31];
        }
    } else {
        // weighted half: sum 4 window partials inline (16 loads per thread)
        const float4* wp4 = reinterpret_cast<const float4*>(g_wpart);
        #pragma unroll
        for (int j = 0; j < 4; j++) {
            const int e = tid + 256 * j;           // e = row*32 + c4
            const size_t idx = (size_t)(e >> 5) * (DD / 4) + (koff >> 2) + (e & 31);
            float4 v0 = wp4[idx];
            float4 v1 = wp4[idx + 1 * (BB * DD / 4)];
            float4 v2 = wp4[idx + 2 * (BB * DD / 4)];
            float4 v3 = wp4[idx + 3 * (BB * DD / 4)];
            float4 s;
            s.x = (v0.x + v1.x) + (v2.x + v3.x);
            s.y = (v0.y + v1.y) + (v2.y + v3.y);
            s.z = (v0.z + v1.z) + (v2.z + v3.z);
            s.w = (v0.w + v1.w) + (v2.w + v3.w);
            sC4[e] = s;
        }
    }
    float4* sW4 = reinterpret_cast<float4*>(&sW[0][0]);
    #pragma unroll
    for (int j = 0; j < 8; j++) {
        const int e = tid + 256 * j;           // e = k*16 + c4
        sW4[e] = reinterpret_cast<const float4*>(
            Wm + (size_t)(kg0 + (e >> 4)) * OO + obase)[e & 15];
    }
    __syncthreads();

    const int oc = tid & 63;       // consecutive within warp -> conflict-free sW
    const int bq = tid >> 6;       // 0..3, each owns 8 batches
    float acc[8];
    #pragma unroll
    for (int i = 0; i < 8; i++) acc[i] = 0.f;

    #pragma unroll 4
    for (int k = 0; k < KT; k++) {
        const float w = sW[k][oc];
        #pragma unroll
        for (int i = 0; i < 8; i++)
            acc[i] += sC[bq * 8 + i][k] * w;   // broadcast reads
    }

    #pragma unroll
    for (int i = 0; i < 8; i++)
        g_part[((size_t)ks * BB + bq * 8 + i) * OO + obase + oc] = acc[i];
}

// ---------------------------------------------------------------------------
// Kernel 4: out[b,o] = tanh(sum_ks part[ks,b,o]). float4, 8192 lanes.
// ---------------------------------------------------------------------------
__global__ void __launch_bounds__(256) out_reduce(float* __restrict__ out) {
    const int i4 = blockIdx.x * 256 + threadIdx.x;
    const float4* p4 = reinterpret_cast<const float4*>(g_part);
    float4 s = make_float4(0.f, 0.f, 0.f, 0.f);
    #pragma unroll
    for (int ks = 0; ks < KS; ks++) {
        float4 v = p4[(size_t)ks * (BB * OO / 4) + i4];
        s.x += v.x; s.y += v.y; s.z += v.z; s.w += v.w;
    }
    float4 r = make_float4(tanhf(s.x), tanhf(s.y), tanhf(s.z), tanhf(s.w));
    reinterpret_cast<float4*>(out)[i4] = r;
}

// ---------------------------------------------------------------------------
extern "C" void kernel_launch(void* const* d_in, const int* in_sizes, int n_in,
                              void* d_out, int out_size) {
    const float* src = (const float*)d_in[0];   // [B,S,D]
    const float* tgt = (const float*)d_in[1];   // [B,D]
    const int*   pos = (const int*)d_in[2];     // [B]
    const float* Wm  = (const float*)d_in[3];   // [2D,O]
    float* out = (float*)d_out;                 // [B,O]

    score_kernel<<<dim3(SS / 64, BB), 256>>>(src, tgt);
    weighted_kernel<<<dim3(DD / 256, BB, WSPLIT), 256>>>(src, pos);
    out_partial<<<dim3(OO / OT, KS), 256>>>(tgt, Wm);
    out_reduce<<<BB * OO / 4 / 256, 256>>>(out);
}